// round 6
// baseline (speedup 1.0000x reference)
#include <cuda_runtime.h>

#define NUM_GRAPHS 2048
#define ND 256
#define ED 128
#define HD 128
#define MAXN 100000
#define MAXE 400000

// Scratch (device globals: allocation-free per harness rules)
__device__ __align__(16) int   g_offsets[NUM_GRAPHS + 1];
__device__ __align__(16) float g_P[NUM_GRAPHS * HD];            // pooled @ W1d  [2048,128]
__device__ __align__(16) float g_AB[(size_t)MAXN * 256];        // [h@W1a | h@W1b] [N,256]
__device__ __align__(16) float g_EC[(size_t)MAXE * 128];        // ea @ W1c       [E,128]

// ---------------------------------------------------------------------------
// Kernel 1: graph start offsets via binary search (batch is sorted int32)
// ---------------------------------------------------------------------------
__global__ void offsets_kernel(const int* __restrict__ batch, int N) {
    int g = blockIdx.x * blockDim.x + threadIdx.x;
    if (g > NUM_GRAPHS) return;
    int lo = 0, hi = N;
    while (lo < hi) {
        int mid = (lo + hi) >> 1;
        if (batch[mid] < g) lo = mid + 1; else hi = mid;
    }
    g_offsets[g] = lo;
}

// ---------------------------------------------------------------------------
// Kernel 2: per-graph mean pooling + P = pooled @ W1d (W1 rows 640..895)
// one block per graph, 128 threads
// ---------------------------------------------------------------------------
__global__ void pool_kernel(const float* __restrict__ h, const float* __restrict__ W1) {
    __shared__ float pool_s[ND];
    int g = blockIdx.x;
    int tid = threadIdx.x;
    int o0 = g_offsets[g], o1 = g_offsets[g + 1];
    float s0 = 0.f, s1 = 0.f;
    for (int r = o0; r < o1; ++r) {
        const float* row = h + (size_t)r * ND;
        s0 += row[tid];
        s1 += row[tid + 128];
    }
    int cnt = o1 - o0;
    float inv = 1.f / (float)(cnt > 1 ? cnt : 1);
    pool_s[tid]       = s0 * inv;
    pool_s[tid + 128] = s1 * inv;
    __syncthreads();
    float acc = 0.f;
    const float* Wg = W1 + (size_t)640 * HD;   // g-block of W1
#pragma unroll 8
    for (int k = 0; k < ND; ++k) acc += pool_s[k] * Wg[k * HD + tid];
    g_P[g * HD + tid] = acc;
}

// ---------------------------------------------------------------------------
// Kernel 3: generic C[m, cbase..cbase+127] = A[m,:K] @ W[:K,0..127]
// BM=128, BN=128, BK=8; 256 threads; 8x8 per thread. Static smem only.
// ---------------------------------------------------------------------------
__global__ void gemm128_kernel(const float* __restrict__ A, int lda,
                               const float* __restrict__ W, int K,
                               float* __restrict__ C, int ldc, int cbase,
                               int M) {
    __shared__ float aT_s[8][132];
    __shared__ float w_s[8][132];
    int tid = threadIdx.x;            // 256
    int m0  = blockIdx.x * 128;
    int r0 = (tid >> 4) * 8;
    int c0 = (tid & 15) * 8;

    float acc[8][8];
#pragma unroll
    for (int i = 0; i < 8; ++i)
#pragma unroll
        for (int j = 0; j < 8; ++j) acc[i][j] = 0.f;

    int lrow = tid >> 1;              // 0..127
    int lcol = (tid & 1) * 4;         // 0 or 4
    int wrow = tid >> 5;              // 0..7
    int wcol = (tid & 31) * 4;        // 0..124

    for (int kt = 0; kt < K; kt += 8) {
        float4 av = make_float4(0.f, 0.f, 0.f, 0.f);
        int m = m0 + lrow;
        if (m < M) av = *(const float4*)(A + (size_t)m * lda + kt + lcol);
        aT_s[lcol + 0][lrow] = av.x;
        aT_s[lcol + 1][lrow] = av.y;
        aT_s[lcol + 2][lrow] = av.z;
        aT_s[lcol + 3][lrow] = av.w;

        *(float4*)&w_s[wrow][wcol] =
            *(const float4*)(W + (size_t)(kt + wrow) * 128 + wcol);
        __syncthreads();

#pragma unroll
        for (int k = 0; k < 8; ++k) {
            float a[8], b[8];
            *(float4*)&a[0] = *(const float4*)&aT_s[k][r0];
            *(float4*)&a[4] = *(const float4*)&aT_s[k][r0 + 4];
            *(float4*)&b[0] = *(const float4*)&w_s[k][c0];
            *(float4*)&b[4] = *(const float4*)&w_s[k][c0 + 4];
#pragma unroll
            for (int i = 0; i < 8; ++i)
#pragma unroll
                for (int j = 0; j < 8; ++j) acc[i][j] += a[i] * b[j];
        }
        __syncthreads();
    }

#pragma unroll
    for (int i = 0; i < 8; ++i) {
        int m = m0 + r0 + i;
        if (m < M) {
            float* dst = C + (size_t)m * ldc + cbase + c0;
            *(float4*)dst       = make_float4(acc[i][0], acc[i][1], acc[i][2], acc[i][3]);
            *(float4*)(dst + 4) = make_float4(acc[i][4], acc[i][5], acc[i][6], acc[i][7]);
        }
    }
}

// ---------------------------------------------------------------------------
// Kernel 4: epilogue. One warp per edge:
//   hid = relu(EC[e] + AB[s][0:128] + AB[t][128:256] + P[batch[s]] + b1)
//   out[e] = hid . W2 + b2
// ---------------------------------------------------------------------------
__global__ void epilogue_kernel(const int* __restrict__ ei,
                                const int* __restrict__ batch,
                                const float* __restrict__ b1,
                                const float* __restrict__ W2,
                                const float* __restrict__ b2,
                                float* __restrict__ out, int E) {
    int warp = (blockIdx.x * blockDim.x + threadIdx.x) >> 5;
    int lane = threadIdx.x & 31;
    if (warp >= E) return;
    int e = warp;

    int s = __ldg(&ei[e]);
    int t = __ldg(&ei[E + e]);
    int b = __ldg(&batch[s]);

    int c = lane * 4;
    float4 ec = *(const float4*)(g_EC + (size_t)e * 128 + c);
    float4 av = __ldg((const float4*)(g_AB + (size_t)s * 256 + c));
    float4 bv = __ldg((const float4*)(g_AB + (size_t)t * 256 + 128 + c));
    float4 pv = __ldg((const float4*)(g_P + b * 128 + c));
    float4 b1v = __ldg((const float4*)(b1 + c));
    float4 w2v = __ldg((const float4*)(W2 + c));

    float partial =
        fmaxf(ec.x + av.x + bv.x + pv.x + b1v.x, 0.f) * w2v.x +
        fmaxf(ec.y + av.y + bv.y + pv.y + b1v.y, 0.f) * w2v.y +
        fmaxf(ec.z + av.z + bv.z + pv.z + b1v.z, 0.f) * w2v.z +
        fmaxf(ec.w + av.w + bv.w + pv.w + b1v.w, 0.f) * w2v.w;

#pragma unroll
    for (int off = 16; off > 0; off >>= 1)
        partial += __shfl_xor_sync(0xffffffffu, partial, off);

    if (lane == 0) out[e] = partial + __ldg(b2);
}

// ---------------------------------------------------------------------------
extern "C" void kernel_launch(void* const* d_in, const int* in_sizes, int n_in,
                              void* d_out, int out_size) {
    const float* h     = (const float*)d_in[0];
    const int*   ei    = (const int*)d_in[1];     // int32! (JAX x64 disabled)
    const float* ea    = (const float*)d_in[2];
    const int*   batch = (const int*)d_in[3];     // int32!
    const float* W1    = (const float*)d_in[4];
    const float* b1    = (const float*)d_in[5];
    const float* W2    = (const float*)d_in[6];
    const float* b2    = (const float*)d_in[7];
    float* out = (float*)d_out;

    int N = in_sizes[0] / ND;
    int E = in_sizes[2] / ED;

    offsets_kernel<<<(NUM_GRAPHS + 256) / 256, 256>>>(batch, N);
    pool_kernel<<<NUM_GRAPHS, 128>>>(h, W1);

    float* AB = nullptr; cudaGetSymbolAddress((void**)&AB, g_AB);
    float* EC = nullptr; cudaGetSymbolAddress((void**)&EC, g_EC);

    int nblk = (N + 127) / 128;
    int eblk = (E + 127) / 128;
    // AB[:,0:128]   = h @ W1[0:256]
    gemm128_kernel<<<nblk, 256>>>(h, ND, W1, 256, AB, 256, 0, N);
    // AB[:,128:256] = h @ W1[256:512]
    gemm128_kernel<<<nblk, 256>>>(h, ND, W1 + (size_t)256 * 128, 256, AB, 256, 128, N);
    // EC = ea @ W1[512:640]
    gemm128_kernel<<<eblk, 256>>>(ea, ED, W1 + (size_t)512 * 128, 128, EC, 128, 0, E);

    int warps_per_block = 8;  // 256 threads
    int gblk = (E + warps_per_block - 1) / warps_per_block;
    epilogue_kernel<<<gblk, 256>>>(ei, batch, b1, W2, b2, out, E);
}